// round 12
// baseline (speedup 1.0000x reference)
#include <cuda_runtime.h>
#include <cuda_bf16.h>
#include <cuda_fp16.h>
#include <cstdint>
#include <math.h>

#define NN   50000
#define EE   300000
#define FIN  16
#define FE   8
#define HH   64
#define HEADS 4
#define NGRP 64
#define KK   1024
#define E2   (EE + NN)
#define NPART 512
#define CHUNKS 16
#define CK   64               // k per chunk
#define NPB  6250             // nodes per Q batch
#define NB   8                // batches

// ---------------- scratch ----------------
// Q ping-pong: [NPB][k/2][hp][2] fp16-pair interleave, 819 MB each
static __device__ __half g_QA[(size_t)NPB * KK * HH];
static __device__ __half g_QB[(size_t)NPB * KK * HH];

static __device__ int   g_cnt[NN];
static __device__ int   g_ptr[NN + 1];
static __device__ int   g_cursor[NN];
static __device__ int   g_eperm[EE];
static __device__ int   g_deg[NN];
static __device__ int   g_ptr2[NN + 1];     // dst CSR
static __device__ int   g_cursor2[NN];
static __device__ int   g_eperm2[EE];
static __device__ float g_agg[NN * HH];
static __device__ float g_h[NN * HH];
static __device__ float g_xh[NN * HH];
static __device__ float g_asrc[NN * HEADS];
static __device__ float g_adst[NN * HEADS];
static __device__ float g_h2[NN * HH];
static __device__ float g_pool[NGRP * HH];
static __device__ int   g_gcnt[NGRP];
static __device__ float g_psum[NPART];
static __device__ float g_psumsq[NPART];
static __device__ float g_stats[4];

__device__ __forceinline__ void cp16(uint32_t dst_s, const void* src_g) {
    asm volatile("cp.async.cg.shared.global [%0], [%1], 16;\n"
                 :: "r"(dst_s), "l"(src_g));
}

// ---------------- CSR by src AND dst ----------------
__global__ void k_hist(const int* __restrict__ ei) {
    int e = blockIdx.x * blockDim.x + threadIdx.x;
    if (e >= EE) return;
    atomicAdd(&g_cnt[ei[e]], 1);
    atomicAdd(&g_deg[ei[EE + e]], 1);
}

__global__ void k_scan() {
    __shared__ int ss[1024];
    const int CH = (NN + 1023) / 1024;
    int t = threadIdx.x;
    int lo = t * CH;
    int hi = lo + CH; if (hi > NN) hi = NN;
    // pass A: src counts -> ptr/cursor
    int s = 0;
    for (int i = lo; i < hi; i++) s += g_cnt[i];
    ss[t] = s;
    __syncthreads();
    for (int off = 1; off < 1024; off <<= 1) {
        int v = (t >= off) ? ss[t - off] : 0;
        __syncthreads();
        ss[t] += v;
        __syncthreads();
    }
    int run = ss[t] - s;
    for (int i = lo; i < hi; i++) {
        g_ptr[i] = run;
        g_cursor[i] = run;
        run += g_cnt[i];
    }
    if (t == 0) g_ptr[NN] = EE;
    __syncthreads();
    // pass B: dst counts (deg) -> ptr2/cursor2
    s = 0;
    for (int i = lo; i < hi; i++) s += g_deg[i];
    ss[t] = s;
    __syncthreads();
    for (int off = 1; off < 1024; off <<= 1) {
        int v = (t >= off) ? ss[t - off] : 0;
        __syncthreads();
        ss[t] += v;
        __syncthreads();
    }
    run = ss[t] - s;
    for (int i = lo; i < hi; i++) {
        g_ptr2[i] = run;
        g_cursor2[i] = run;
        run += g_deg[i];
    }
    if (t == 0) g_ptr2[NN] = EE;
}

__global__ void k_scatter(const int* __restrict__ ei) {
    int e = blockIdx.x * blockDim.x + threadIdx.x;
    if (e >= EE) return;
    int pos = atomicAdd(&g_cursor[ei[e]], 1);
    g_eperm[pos] = e;
    int pos2 = atomicAdd(&g_cursor2[ei[EE + e]], 1);
    g_eperm2[pos2] = e;
}

// ---- Q[nl][kp][hp][2] = sum_f x[n0+nl,f] * W2[k, f*64+h]  (fp16 batch) ----
__global__ void __launch_bounds__(256)
k_Q(const float* __restrict__ x, const float* __restrict__ w2, int n0, int which) {
    __half2* q = (__half2*)(which ? g_QB : g_QA);
    int kl = threadIdx.x >> 5;
    int hp = threadIdx.x & 31;
    int kg  = blockIdx.y * 8 + kl;       // 0..511
    int kg2 = kg + 512;                  // 512..1023
    int nl0 = blockIdx.x * 32;

    __shared__ float2 xs2[32 * 16];
    for (int i = threadIdx.x; i < 512; i += 256) {
        int nl = i >> 4, f = i & 15;
        int n = n0 + nl0 + nl;
        float v = (n < NN) ? x[n * 16 + f] : 0.f;
        xs2[i] = make_float2(v, v);
    }

    unsigned long long wp[16], wq[16];
#pragma unroll
    for (int f = 0; f < 16; f++) {
        wp[f] = *(const unsigned long long*)(w2 + (size_t)kg  * 1024 + f * 64 + hp * 2);
        wq[f] = *(const unsigned long long*)(w2 + (size_t)kg2 * 1024 + f * 64 + hp * 2);
    }
    __syncthreads();

    size_t offA = (size_t)(kg  >> 1) * 64 + (hp << 1) + (kg  & 1);
    size_t offB = (size_t)(kg2 >> 1) * 64 + (hp << 1) + (kg2 & 1);

#pragma unroll 2
    for (int nl = 0; nl < 32; nl++) {
        if (nl0 + nl >= NPB) break;
        unsigned long long accA = 0ULL, accB = 0ULL;
        const unsigned long long* xp = (const unsigned long long*)(xs2 + nl * 16);
#pragma unroll
        for (int f = 0; f < 16; f++) {
            unsigned long long xv = xp[f];
            asm("fma.rn.f32x2 %0, %1, %2, %0;" : "+l"(accA) : "l"(xv), "l"(wp[f]));
            asm("fma.rn.f32x2 %0, %1, %2, %0;" : "+l"(accB) : "l"(xv), "l"(wq[f]));
        }
        float loA, hiA, loB, hiB;
        asm("mov.b64 {%0,%1}, %2;" : "=f"(loA), "=f"(hiA) : "l"(accA));
        asm("mov.b64 {%0,%1}, %2;" : "=f"(loB), "=f"(hiB) : "l"(accB));
        size_t nb = (size_t)(nl0 + nl) * 32768;
        q[nb + offA] = __floats2half2_rn(loA, hiA);
        q[nb + offB] = __floats2half2_rn(loB, hiB);
    }
}

// ---- per-edge message: msg = r_e @ Q_src + x_src@b2'  (packed f32x2 dot) ----
__global__ void k_msg(const float* __restrict__ x, const float* __restrict__ ea,
                      const int* __restrict__ ei, const float* __restrict__ w1,
                      const float* __restrict__ b1, const float* __restrict__ b2,
                      int n0, int which) {
    const __half* qb0 = which ? g_QB : g_QA;
    int nl = blockIdx.x;
    int n = n0 + nl;
    int p0 = g_ptr[n], p1 = g_ptr[n + 1];
    if (p0 == p1) return;

    __shared__ __align__(16) uint2 qbuf[2][(CK / 2) * 32];   // 2 x 8KB
    __shared__ __align__(16) float2 r_s2[8][2][CK];          // (r,r) pairs, 8KB
    __shared__ float bx[64];

    int tid = threadIdx.x;
    int wid = tid >> 5, lane = tid & 31;

    if (tid < 64) {
        float s = 0.f;
        const float* xv = x + n * 16;
#pragma unroll
        for (int f = 0; f < 16; f++) s = fmaf(xv[f], b2[f * 64 + tid], s);
        bx[tid] = s;
    }

    const char* qg = (const char*)qb0 + (size_t)nl * (KK * HH * 2);
    uint32_t sbase = (uint32_t)__cvta_generic_to_shared(&qbuf[0][0]);
    uint32_t soff = tid * 16;

    for (int ebase = p0; ebase < p1; ebase += 16) {
        int t0 = ebase + wid, t1 = ebase + 8 + wid;
        bool e0v = t0 < p1, e1v = t1 < p1;
        int dst0 = 0, dst1 = 0;
        float ev0[8], ev1[8];
        if (e0v) {
            int e = g_eperm[t0];
            dst0 = ei[EE + e];
            const float4* p = (const float4*)(ea + (size_t)e * 8);
            float4 u = p[0], v = p[1];
            ev0[0]=u.x; ev0[1]=u.y; ev0[2]=u.z; ev0[3]=u.w;
            ev0[4]=v.x; ev0[5]=v.y; ev0[6]=v.z; ev0[7]=v.w;
        }
        if (e1v) {
            int e = g_eperm[t1];
            dst1 = ei[EE + e];
            const float4* p = (const float4*)(ea + (size_t)e * 8);
            float4 u = p[0], v = p[1];
            ev1[0]=u.x; ev1[1]=u.y; ev1[2]=u.z; ev1[3]=u.w;
            ev1[4]=v.x; ev1[5]=v.y; ev1[6]=v.z; ev1[7]=v.w;
        }
        unsigned long long acc0 = 0ULL, acc1 = 0ULL;   // (a_even,a_odd) packed

        // prefetch chunk 0
        {
            uint32_t d = sbase + soff;
            const char* s = qg + soff;
            cp16(d, s); cp16(d + 4096, s + 4096);
            asm volatile("cp.async.commit_group;");
        }

        for (int c = 0; c < CHUNKS; c++) {
            if (c + 1 < CHUNKS) {
                uint32_t d = sbase + ((c + 1) & 1) * 8192 + soff;
                const char* s = qg + (c + 1) * 8192 + soff;
                cp16(d, s); cp16(d + 4096, s + 4096);
                asm volatile("cp.async.commit_group;");
                asm volatile("cp.async.wait_group 1;");
            } else {
                asm volatile("cp.async.wait_group 0;");
            }
            __syncthreads();

            if (e0v) {
#pragma unroll
                for (int j = 0; j < 2; j++) {
                    int k = c * 64 + j * 32 + lane;
                    float a = b1[k];
#pragma unroll
                    for (int f = 0; f < 8; f++) a = fmaf(ev0[f], w1[f * 1024 + k], a);
                    a = fmaxf(a, 0.f);
                    r_s2[wid][0][j * 32 + lane] = make_float2(a, a);
                }
            }
            if (e1v) {
#pragma unroll
                for (int j = 0; j < 2; j++) {
                    int k = c * 64 + j * 32 + lane;
                    float a = b1[k];
#pragma unroll
                    for (int f = 0; f < 8; f++) a = fmaf(ev1[f], w1[f * 1024 + k], a);
                    a = fmaxf(a, 0.f);
                    r_s2[wid][1][j * 32 + lane] = make_float2(a, a);
                }
            }
            __syncwarp();

            const uint2* qc = qbuf[c & 1];
            const ulonglong2* rp0 = (const ulonglong2*)r_s2[wid][0];
            const ulonglong2* rp1 = (const ulonglong2*)r_s2[wid][1];
            if (e0v) {
#pragma unroll 8
                for (int kp = 0; kp < CK / 2; kp++) {
                    uint2 v = qc[kp * 32 + lane];
                    float2 fa = __half22float2(*(const __half2*)&v.x); // k=2kp
                    float2 fb = __half22float2(*(const __half2*)&v.y); // k=2kp+1
                    unsigned long long qa, qb;
                    asm("mov.b64 %0, {%1,%2};" : "=l"(qa) : "f"(fa.x), "f"(fa.y));
                    asm("mov.b64 %0, {%1,%2};" : "=l"(qb) : "f"(fb.x), "f"(fb.y));
                    ulonglong2 ra = rp0[kp];
                    asm("fma.rn.f32x2 %0, %1, %2, %0;" : "+l"(acc0) : "l"(ra.x), "l"(qa));
                    asm("fma.rn.f32x2 %0, %1, %2, %0;" : "+l"(acc0) : "l"(ra.y), "l"(qb));
                    if (e1v) {
                        ulonglong2 rb = rp1[kp];
                        asm("fma.rn.f32x2 %0, %1, %2, %0;" : "+l"(acc1) : "l"(rb.x), "l"(qa));
                        asm("fma.rn.f32x2 %0, %1, %2, %0;" : "+l"(acc1) : "l"(rb.y), "l"(qb));
                    }
                }
            }
            __syncthreads();
        }

        int h0 = lane * 2;
        if (e0v) {
            float a00, a01;
            asm("mov.b64 {%0,%1}, %2;" : "=f"(a00), "=f"(a01) : "l"(acc0));
            atomicAdd(&g_agg[(size_t)dst0 * 64 + h0],     a00 + bx[h0]);
            atomicAdd(&g_agg[(size_t)dst0 * 64 + h0 + 1], a01 + bx[h0 + 1]);
        }
        if (e1v) {
            float a10, a11;
            asm("mov.b64 {%0,%1}, %2;" : "=f"(a10), "=f"(a11) : "l"(acc1));
            atomicAdd(&g_agg[(size_t)dst1 * 64 + h0],     a10 + bx[h0]);
            atomicAdd(&g_agg[(size_t)dst1 * 64 + h0 + 1], a11 + bx[h0 + 1]);
        }
    }
}

// ---------------- NNConv epilogue ----------------
__global__ void k_conv(const float* __restrict__ x, const float* __restrict__ rw,
                       const float* __restrict__ cb) {
    int i = blockIdx.x * blockDim.x + threadIdx.x;
    if (i >= NN * HH) return;
    int n = i >> 6, j = i & 63;
    float d = fmaxf((float)g_deg[n], 1.f);
    float v = cb[j] + g_agg[i] / d;
    const float* xv = x + n * 16;
#pragma unroll
    for (int f = 0; f < 16; f++) v = fmaf(xv[f], rw[f * 64 + j], v);
    g_h[i] = fmaxf(v, 0.f);
}

// ---------------- graph layernorm reductions ----------------
__global__ void k_redpart(int which) {
    const float* src = which ? g_h2 : g_h;
    float s = 0.f, q = 0.f;
    for (int i = blockIdx.x * blockDim.x + threadIdx.x; i < NN * HH;
         i += NPART * 256) {
        float v = src[i];
        s += v; q = fmaf(v, v, q);
    }
    __shared__ float bs[256], bq[256];
    bs[threadIdx.x] = s; bq[threadIdx.x] = q;
    __syncthreads();
    for (int off = 128; off; off >>= 1) {
        if (threadIdx.x < off) {
            bs[threadIdx.x] += bs[threadIdx.x + off];
            bq[threadIdx.x] += bq[threadIdx.x + off];
        }
        __syncthreads();
    }
    if (threadIdx.x == 0) { g_psum[blockIdx.x] = bs[0]; g_psumsq[blockIdx.x] = bq[0]; }
}

__global__ void k_redfin(int which) {
    __shared__ double ds[NPART], dq[NPART];
    int t = threadIdx.x;
    ds[t] = (double)g_psum[t];
    dq[t] = (double)g_psumsq[t];
    __syncthreads();
    for (int off = NPART / 2; off; off >>= 1) {
        if (t < off) { ds[t] += ds[t + off]; dq[t] += dq[t + off]; }
        __syncthreads();
    }
    if (t == 0) {
        double M = (double)NN * HH;
        double mu = ds[0] / M;
        double var = dq[0] / M - mu * mu;
        if (var < 0.0) var = 0.0;
        float inv = 1.f / ((float)sqrt(var) + 1e-5f);
        g_stats[2 * which]     = (float)mu;
        g_stats[2 * which + 1] = inv;
    }
}

// ---------------- GAT prep: LN1 apply, xh = hn@gat_w, attn dots ----------
__global__ void k_gatprep(const float* __restrict__ gw, const float* __restrict__ asv,
                          const float* __restrict__ adv, const float* __restrict__ n1w,
                          const float* __restrict__ n1b) {
    int n = blockIdx.x, t = threadIdx.x;
    __shared__ float hs[64];
    float mu = g_stats[0], inv = g_stats[1];
    hs[t] = (g_h[(size_t)n * 64 + t] - mu) * inv * n1w[t] + n1b[t];
    __syncthreads();
    float v = 0.f;
#pragma unroll
    for (int i = 0; i < 64; i++) v = fmaf(hs[i], gw[i * 64 + t], v);
    g_xh[(size_t)n * 64 + t] = v;
    int hd = t >> 4, dd = t & 15;
    float ps = v * asv[t];
    float pd = v * adv[t];
#pragma unroll
    for (int off = 8; off; off >>= 1) {
        ps += __shfl_down_sync(0xffffffffu, ps, off, 16);
        pd += __shfl_down_sync(0xffffffffu, pd, off, 16);
    }
    if (dd == 0) {
        g_asrc[n * 4 + hd] = ps;
        g_adst[n * 4 + hd] = pd;
    }
}

// ---------------- fused GAT via dst-CSR: no atomics, no alpha array -------
__global__ void k_gatfused(const int* __restrict__ ei, const float* __restrict__ gb) {
    int n = blockIdx.x, t = threadIdx.x;
    int hd = t >> 4;
    int p0 = g_ptr2[n], p1 = g_ptr2[n + 1];
    float adst_n = g_adst[n * 4 + hd];

    // pass 1: max over self-loop + incoming edges
    float a_self = g_asrc[n * 4 + hd] + adst_n;
    a_self = (a_self > 0.f) ? a_self : 0.2f * a_self;
    float amax = a_self;
    for (int p = p0; p < p1; p++) {
        int s = ei[g_eperm2[p]];
        float a = g_asrc[s * 4 + hd] + adst_n;
        a = (a > 0.f) ? a : 0.2f * a;
        amax = fmaxf(amax, a);
    }
    // pass 2: exp-weighted aggregation
    float w = expf(a_self - amax);
    float sum = w;
    float acc = w * g_xh[(size_t)n * 64 + t];
    for (int p = p0; p < p1; p++) {
        int s = ei[g_eperm2[p]];
        float a = g_asrc[s * 4 + hd] + adst_n;
        a = (a > 0.f) ? a : 0.2f * a;
        float ww = expf(a - amax);
        sum += ww;
        acc = fmaf(ww, g_xh[(size_t)s * 64 + t], acc);
    }
    g_h2[(size_t)n * 64 + t] = fmaxf(acc / (sum + 1e-16f) + gb[t], 0.f);
}

__global__ void k_pool(const int* __restrict__ batch, const float* __restrict__ n2w,
                       const float* __restrict__ n2b) {
    int i = blockIdx.x * blockDim.x + threadIdx.x;
    if (i >= NN * HH) return;
    int n = i >> 6, j = i & 63;
    float v = (g_h2[i] - g_stats[2]) * g_stats[3] * n2w[j] + n2b[j];
    int g = batch[n];
    atomicAdd(&g_pool[g * 64 + j], v);
    if (j == 0) atomicAdd(&g_gcnt[g], 1);
}

__global__ void k_head(const float* __restrict__ lw, const float* __restrict__ lb,
                       float* __restrict__ out) {
    int g = blockIdx.x, t = threadIdx.x;
    float c = fmaxf((float)g_gcnt[g], 1.f);
    float v = (g_pool[g * 64 + t] / c) * lw[t];
    __shared__ float sm[64];
    sm[t] = v;
    __syncthreads();
    for (int off = 32; off; off >>= 1) {
        if (t < off) sm[t] += sm[t + off];
        __syncthreads();
    }
    if (t == 0) out[g] = sm[0] + lb[0];
}

// ---------------- launch ----------------
extern "C" void kernel_launch(void* const* d_in, const int* in_sizes, int n_in,
                              void* d_out, int out_size) {
    const float* x    = (const float*)d_in[0];
    const int*   ei   = (const int*)d_in[1];
    const float* ea   = (const float*)d_in[2];
    const int*   batch= (const int*)d_in[3];
    const float* enw1 = (const float*)d_in[4];
    const float* enb1 = (const float*)d_in[5];
    const float* enw2 = (const float*)d_in[6];
    const float* enb2 = (const float*)d_in[7];
    const float* rootw= (const float*)d_in[8];
    const float* convb= (const float*)d_in[9];
    const float* n1w  = (const float*)d_in[10];
    const float* n1b  = (const float*)d_in[11];
    const float* gatw = (const float*)d_in[12];
    const float* attS = (const float*)d_in[13];
    const float* attD = (const float*)d_in[14];
    const float* gatb = (const float*)d_in[15];
    const float* n2w  = (const float*)d_in[16];
    const float* n2b  = (const float*)d_in[17];
    const float* linw = (const float*)d_in[18];
    const float* linb = (const float*)d_in[19];
    float* out = (float*)d_out;

    static void *p_agg = 0, *p_cnt = 0, *p_deg = 0, *p_pool = 0, *p_gcnt = 0;
    static cudaStream_t s2;
    static cudaEvent_t ev_begin, evq[NB], evm[NB];
    static int init_done = 0;
    if (!init_done) {
        cudaGetSymbolAddress(&p_agg,  g_agg);
        cudaGetSymbolAddress(&p_cnt,  g_cnt);
        cudaGetSymbolAddress(&p_deg,  g_deg);
        cudaGetSymbolAddress(&p_pool, g_pool);
        cudaGetSymbolAddress(&p_gcnt, g_gcnt);
        cudaStreamCreateWithFlags(&s2, cudaStreamNonBlocking);
        cudaEventCreateWithFlags(&ev_begin, cudaEventDisableTiming);
        for (int b = 0; b < NB; b++) {
            cudaEventCreateWithFlags(&evq[b], cudaEventDisableTiming);
            cudaEventCreateWithFlags(&evm[b], cudaEventDisableTiming);
        }
        init_done = 1;
    }

    cudaMemsetAsync(p_agg,  0, (size_t)NN * HH * 4, 0);
    cudaMemsetAsync(p_cnt,  0, (size_t)NN * 4, 0);
    cudaMemsetAsync(p_deg,  0, (size_t)NN * 4, 0);
    cudaMemsetAsync(p_pool, 0, (size_t)NGRP * HH * 4, 0);
    cudaMemsetAsync(p_gcnt, 0, (size_t)NGRP * 4, 0);

    k_hist<<<(EE + 255) / 256, 256>>>(ei);
    k_scan<<<1, 1024>>>();
    k_scatter<<<(EE + 255) / 256, 256>>>(ei);

    // fork producer stream after CSR build
    cudaEventRecord(ev_begin, 0);
    cudaStreamWaitEvent(s2, ev_begin, 0);

    dim3 qg((NPB + 31) / 32, 64);
    for (int b = 0; b < NB; b++) {
        int n0 = b * NPB;
        int which = b & 1;
        if (b >= 2) cudaStreamWaitEvent(s2, evm[b - 2], 0);  // buffer free?
        k_Q<<<qg, 256, 0, s2>>>(x, enw2, n0, which);
        cudaEventRecord(evq[b], s2);
        cudaStreamWaitEvent(0, evq[b], 0);                   // Q ready?
        k_msg<<<NPB, 256>>>(x, ea, ei, enw1, enb1, enb2, n0, which);
        cudaEventRecord(evm[b], 0);
    }

    k_conv<<<(NN * HH + 255) / 256, 256>>>(x, rootw, convb);

    k_redpart<<<NPART, 256>>>(0);
    k_redfin<<<1, NPART>>>(0);

    k_gatprep<<<NN, 64>>>(gatw, attS, attD, n1w, n1b);
    k_gatfused<<<NN, 64>>>(ei, gatb);

    k_redpart<<<NPART, 256>>>(1);
    k_redfin<<<1, NPART>>>(1);

    k_pool<<<(NN * HH + 255) / 256, 256>>>(batch, n2w, n2b);
    k_head<<<NGRP, 64>>>(linw, linb, out);
}

// round 13
// speedup vs baseline: 1.0572x; 1.0572x over previous
#include <cuda_runtime.h>
#include <cuda_bf16.h>
#include <cuda_fp16.h>
#include <cstdint>
#include <math.h>

#define NN   50000
#define EE   300000
#define FIN  16
#define FE   8
#define HH   64
#define HEADS 4
#define NGRP 64
#define KK   1024
#define E2   (EE + NN)
#define NPART 512
#define CHUNKS 16
#define CK   64               // k per chunk
#define NPB  6250             // nodes per Q batch
#define NB   8                // batches

// ---------------- scratch ----------------
// Q ping-pong: [NPB][k/2][hp][2] fp16-pair interleave, 819 MB each
static __device__ __half g_QA[(size_t)NPB * KK * HH];
static __device__ __half g_QB[(size_t)NPB * KK * HH];

static __device__ int   g_cnt[NN];
static __device__ int   g_ptr[NN + 1];
static __device__ int   g_cursor[NN];
static __device__ int   g_eperm[EE];
static __device__ int   g_deg[NN];
static __device__ int   g_ptr2[NN + 1];     // dst CSR
static __device__ int   g_cursor2[NN];
static __device__ int   g_eperm2[EE];
static __device__ float g_agg[NN * HH];
static __device__ float g_h[NN * HH];
static __device__ float g_xh[NN * HH];
static __device__ float g_asrc[NN * HEADS];
static __device__ float g_adst[NN * HEADS];
static __device__ float g_h2[NN * HH];
static __device__ float g_pool[NGRP * HH];
static __device__ int   g_gcnt[NGRP];
static __device__ float g_psum[NPART];
static __device__ float g_psumsq[NPART];
static __device__ float g_stats[4];

__device__ __forceinline__ void cp16(uint32_t dst_s, const void* src_g) {
    asm volatile("cp.async.cg.shared.global [%0], [%1], 16;\n"
                 :: "r"(dst_s), "l"(src_g));
}

// ---------------- CSR by src AND dst ----------------
__global__ void k_hist(const int* __restrict__ ei) {
    int e = blockIdx.x * blockDim.x + threadIdx.x;
    if (e >= EE) return;
    atomicAdd(&g_cnt[ei[e]], 1);
    atomicAdd(&g_deg[ei[EE + e]], 1);
}

__global__ void k_scan() {
    __shared__ int ss[1024];
    const int CH = (NN + 1023) / 1024;
    int t = threadIdx.x;
    int lo = t * CH;
    int hi = lo + CH; if (hi > NN) hi = NN;
    // pass A: src counts -> ptr/cursor
    int s = 0;
    for (int i = lo; i < hi; i++) s += g_cnt[i];
    ss[t] = s;
    __syncthreads();
    for (int off = 1; off < 1024; off <<= 1) {
        int v = (t >= off) ? ss[t - off] : 0;
        __syncthreads();
        ss[t] += v;
        __syncthreads();
    }
    int run = ss[t] - s;
    for (int i = lo; i < hi; i++) {
        g_ptr[i] = run;
        g_cursor[i] = run;
        run += g_cnt[i];
    }
    if (t == 0) g_ptr[NN] = EE;
    __syncthreads();
    // pass B: dst counts (deg) -> ptr2/cursor2
    s = 0;
    for (int i = lo; i < hi; i++) s += g_deg[i];
    ss[t] = s;
    __syncthreads();
    for (int off = 1; off < 1024; off <<= 1) {
        int v = (t >= off) ? ss[t - off] : 0;
        __syncthreads();
        ss[t] += v;
        __syncthreads();
    }
    run = ss[t] - s;
    for (int i = lo; i < hi; i++) {
        g_ptr2[i] = run;
        g_cursor2[i] = run;
        run += g_deg[i];
    }
    if (t == 0) g_ptr2[NN] = EE;
}

__global__ void k_scatter(const int* __restrict__ ei) {
    int e = blockIdx.x * blockDim.x + threadIdx.x;
    if (e >= EE) return;
    int pos = atomicAdd(&g_cursor[ei[e]], 1);
    g_eperm[pos] = e;
    int pos2 = atomicAdd(&g_cursor2[ei[EE + e]], 1);
    g_eperm2[pos2] = e;
}

// ---- Q[nl][kp][hp][2] = sum_f x[n0+nl,f] * W2[k, f*64+h]  (fp16 batch) ----
__global__ void __launch_bounds__(256)
k_Q(const float* __restrict__ x, const float* __restrict__ w2, int n0, int which) {
    __half2* q = (__half2*)(which ? g_QB : g_QA);
    int kl = threadIdx.x >> 5;
    int hp = threadIdx.x & 31;
    int kg  = blockIdx.y * 8 + kl;       // 0..511
    int kg2 = kg + 512;                  // 512..1023
    int nl0 = blockIdx.x * 32;

    __shared__ float2 xs2[32 * 16];
    for (int i = threadIdx.x; i < 512; i += 256) {
        int nl = i >> 4, f = i & 15;
        int n = n0 + nl0 + nl;
        float v = (n < NN) ? x[n * 16 + f] : 0.f;
        xs2[i] = make_float2(v, v);
    }

    unsigned long long wp[16], wq[16];
#pragma unroll
    for (int f = 0; f < 16; f++) {
        wp[f] = *(const unsigned long long*)(w2 + (size_t)kg  * 1024 + f * 64 + hp * 2);
        wq[f] = *(const unsigned long long*)(w2 + (size_t)kg2 * 1024 + f * 64 + hp * 2);
    }
    __syncthreads();

    size_t offA = (size_t)(kg  >> 1) * 64 + (hp << 1) + (kg  & 1);
    size_t offB = (size_t)(kg2 >> 1) * 64 + (hp << 1) + (kg2 & 1);

#pragma unroll 2
    for (int nl = 0; nl < 32; nl++) {
        if (nl0 + nl >= NPB) break;
        unsigned long long accA = 0ULL, accB = 0ULL;
        const unsigned long long* xp = (const unsigned long long*)(xs2 + nl * 16);
#pragma unroll
        for (int f = 0; f < 16; f++) {
            unsigned long long xv = xp[f];
            asm("fma.rn.f32x2 %0, %1, %2, %0;" : "+l"(accA) : "l"(xv), "l"(wp[f]));
            asm("fma.rn.f32x2 %0, %1, %2, %0;" : "+l"(accB) : "l"(xv), "l"(wq[f]));
        }
        float loA, hiA, loB, hiB;
        asm("mov.b64 {%0,%1}, %2;" : "=f"(loA), "=f"(hiA) : "l"(accA));
        asm("mov.b64 {%0,%1}, %2;" : "=f"(loB), "=f"(hiB) : "l"(accB));
        size_t nb = (size_t)(nl0 + nl) * 32768;
        q[nb + offA] = __floats2half2_rn(loA, hiA);
        q[nb + offB] = __floats2half2_rn(loB, hiB);
    }
}

// ---- per-edge message: msg = r_e @ Q_src + x_src@b2'  (R11 scalar dot) ----
__global__ void k_msg(const float* __restrict__ x, const float* __restrict__ ea,
                      const int* __restrict__ ei, const float* __restrict__ w1,
                      const float* __restrict__ b1, const float* __restrict__ b2,
                      int n0, int which) {
    const __half* qb0 = which ? g_QB : g_QA;
    int nl = blockIdx.x;
    int n = n0 + nl;
    int p0 = g_ptr[n], p1 = g_ptr[n + 1];
    if (p0 == p1) return;

    __shared__ __align__(16) uint2 qbuf[2][(CK / 2) * 32];   // 2 x 8KB
    __shared__ __align__(8) float r_s[8][2][CK];
    __shared__ float bx[64];

    int tid = threadIdx.x;
    int wid = tid >> 5, lane = tid & 31;

    if (tid < 64) {
        float s = 0.f;
        const float* xv = x + n * 16;
#pragma unroll
        for (int f = 0; f < 16; f++) s = fmaf(xv[f], b2[f * 64 + tid], s);
        bx[tid] = s;
    }

    const char* qg = (const char*)qb0 + (size_t)nl * (KK * HH * 2);
    uint32_t sbase = (uint32_t)__cvta_generic_to_shared(&qbuf[0][0]);
    uint32_t soff = tid * 16;

    for (int ebase = p0; ebase < p1; ebase += 16) {
        int t0 = ebase + wid, t1 = ebase + 8 + wid;
        bool e0v = t0 < p1, e1v = t1 < p1;
        int dst0 = 0, dst1 = 0;
        float ev0[8], ev1[8];
        if (e0v) {
            int e = g_eperm[t0];
            dst0 = ei[EE + e];
            const float4* p = (const float4*)(ea + (size_t)e * 8);
            float4 u = p[0], v = p[1];
            ev0[0]=u.x; ev0[1]=u.y; ev0[2]=u.z; ev0[3]=u.w;
            ev0[4]=v.x; ev0[5]=v.y; ev0[6]=v.z; ev0[7]=v.w;
        }
        if (e1v) {
            int e = g_eperm[t1];
            dst1 = ei[EE + e];
            const float4* p = (const float4*)(ea + (size_t)e * 8);
            float4 u = p[0], v = p[1];
            ev1[0]=u.x; ev1[1]=u.y; ev1[2]=u.z; ev1[3]=u.w;
            ev1[4]=v.x; ev1[5]=v.y; ev1[6]=v.z; ev1[7]=v.w;
        }
        float a00 = 0.f, a01 = 0.f, a10 = 0.f, a11 = 0.f;

        // prefetch chunk 0
        {
            uint32_t d = sbase + soff;
            const char* s = qg + soff;
            cp16(d, s); cp16(d + 4096, s + 4096);
            asm volatile("cp.async.commit_group;");
        }

        for (int c = 0; c < CHUNKS; c++) {
            if (c + 1 < CHUNKS) {
                uint32_t d = sbase + ((c + 1) & 1) * 8192 + soff;
                const char* s = qg + (c + 1) * 8192 + soff;
                cp16(d, s); cp16(d + 4096, s + 4096);
                asm volatile("cp.async.commit_group;");
                asm volatile("cp.async.wait_group 1;");
            } else {
                asm volatile("cp.async.wait_group 0;");
            }
            __syncthreads();

            if (e0v) {
#pragma unroll
                for (int j = 0; j < 2; j++) {
                    int k = c * 64 + j * 32 + lane;
                    float a = b1[k];
#pragma unroll
                    for (int f = 0; f < 8; f++) a = fmaf(ev0[f], w1[f * 1024 + k], a);
                    r_s[wid][0][j * 32 + lane] = fmaxf(a, 0.f);
                }
            }
            if (e1v) {
#pragma unroll
                for (int j = 0; j < 2; j++) {
                    int k = c * 64 + j * 32 + lane;
                    float a = b1[k];
#pragma unroll
                    for (int f = 0; f < 8; f++) a = fmaf(ev1[f], w1[f * 1024 + k], a);
                    r_s[wid][1][j * 32 + lane] = fmaxf(a, 0.f);
                }
            }
            __syncwarp();

            const uint2* qc = qbuf[c & 1];
            const float2* rr0 = (const float2*)r_s[wid][0];
            const float2* rr1 = (const float2*)r_s[wid][1];
            if (e0v) {
#pragma unroll 8
                for (int kp = 0; kp < CK / 2; kp++) {
                    uint2 v = qc[kp * 32 + lane];
                    float2 qa = __half22float2(*(const __half2*)&v.x);
                    float2 qb = __half22float2(*(const __half2*)&v.y);
                    float2 r0 = rr0[kp];
                    a00 = fmaf(r0.x, qa.x, a00);
                    a01 = fmaf(r0.x, qa.y, a01);
                    a00 = fmaf(r0.y, qb.x, a00);
                    a01 = fmaf(r0.y, qb.y, a01);
                    if (e1v) {
                        float2 r1 = rr1[kp];
                        a10 = fmaf(r1.x, qa.x, a10);
                        a11 = fmaf(r1.x, qa.y, a11);
                        a10 = fmaf(r1.y, qb.x, a10);
                        a11 = fmaf(r1.y, qb.y, a11);
                    }
                }
            }
            __syncthreads();
        }

        int h0 = lane * 2;
        if (e0v) {
            atomicAdd(&g_agg[(size_t)dst0 * 64 + h0],     a00 + bx[h0]);
            atomicAdd(&g_agg[(size_t)dst0 * 64 + h0 + 1], a01 + bx[h0 + 1]);
        }
        if (e1v) {
            atomicAdd(&g_agg[(size_t)dst1 * 64 + h0],     a10 + bx[h0]);
            atomicAdd(&g_agg[(size_t)dst1 * 64 + h0 + 1], a11 + bx[h0 + 1]);
        }
    }
}

// ---------------- NNConv epilogue ----------------
__global__ void k_conv(const float* __restrict__ x, const float* __restrict__ rw,
                       const float* __restrict__ cb) {
    int i = blockIdx.x * blockDim.x + threadIdx.x;
    if (i >= NN * HH) return;
    int n = i >> 6, j = i & 63;
    float d = fmaxf((float)g_deg[n], 1.f);
    float v = cb[j] + g_agg[i] / d;
    const float* xv = x + n * 16;
#pragma unroll
    for (int f = 0; f < 16; f++) v = fmaf(xv[f], rw[f * 64 + j], v);
    g_h[i] = fmaxf(v, 0.f);
}

// ---------------- graph layernorm reductions ----------------
__global__ void k_redpart(int which) {
    const float* src = which ? g_h2 : g_h;
    float s = 0.f, q = 0.f;
    for (int i = blockIdx.x * blockDim.x + threadIdx.x; i < NN * HH;
         i += NPART * 256) {
        float v = src[i];
        s += v; q = fmaf(v, v, q);
    }
    __shared__ float bs[256], bq[256];
    bs[threadIdx.x] = s; bq[threadIdx.x] = q;
    __syncthreads();
    for (int off = 128; off; off >>= 1) {
        if (threadIdx.x < off) {
            bs[threadIdx.x] += bs[threadIdx.x + off];
            bq[threadIdx.x] += bq[threadIdx.x + off];
        }
        __syncthreads();
    }
    if (threadIdx.x == 0) { g_psum[blockIdx.x] = bs[0]; g_psumsq[blockIdx.x] = bq[0]; }
}

__global__ void k_redfin(int which) {
    __shared__ double ds[NPART], dq[NPART];
    int t = threadIdx.x;
    ds[t] = (double)g_psum[t];
    dq[t] = (double)g_psumsq[t];
    __syncthreads();
    for (int off = NPART / 2; off; off >>= 1) {
        if (t < off) { ds[t] += ds[t + off]; dq[t] += dq[t + off]; }
        __syncthreads();
    }
    if (t == 0) {
        double M = (double)NN * HH;
        double mu = ds[0] / M;
        double var = dq[0] / M - mu * mu;
        if (var < 0.0) var = 0.0;
        float inv = 1.f / ((float)sqrt(var) + 1e-5f);
        g_stats[2 * which]     = (float)mu;
        g_stats[2 * which + 1] = inv;
    }
}

// ---------------- GAT prep: LN1 apply, xh = hn@gat_w, attn dots ----------
__global__ void k_gatprep(const float* __restrict__ gw, const float* __restrict__ asv,
                          const float* __restrict__ adv, const float* __restrict__ n1w,
                          const float* __restrict__ n1b) {
    int n = blockIdx.x, t = threadIdx.x;
    __shared__ float hs[64];
    float mu = g_stats[0], inv = g_stats[1];
    hs[t] = (g_h[(size_t)n * 64 + t] - mu) * inv * n1w[t] + n1b[t];
    __syncthreads();
    float v = 0.f;
#pragma unroll
    for (int i = 0; i < 64; i++) v = fmaf(hs[i], gw[i * 64 + t], v);
    g_xh[(size_t)n * 64 + t] = v;
    int hd = t >> 4, dd = t & 15;
    float ps = v * asv[t];
    float pd = v * adv[t];
#pragma unroll
    for (int off = 8; off; off >>= 1) {
        ps += __shfl_down_sync(0xffffffffu, ps, off, 16);
        pd += __shfl_down_sync(0xffffffffu, pd, off, 16);
    }
    if (dd == 0) {
        g_asrc[n * 4 + hd] = ps;
        g_adst[n * 4 + hd] = pd;
    }
}

// ---------------- fused GAT via dst-CSR: no atomics, no alpha array -------
__global__ void k_gatfused(const int* __restrict__ ei, const float* __restrict__ gb) {
    int n = blockIdx.x, t = threadIdx.x;
    int hd = t >> 4;
    int p0 = g_ptr2[n], p1 = g_ptr2[n + 1];
    float adst_n = g_adst[n * 4 + hd];

    // pass 1: max over self-loop + incoming edges
    float a_self = g_asrc[n * 4 + hd] + adst_n;
    a_self = (a_self > 0.f) ? a_self : 0.2f * a_self;
    float amax = a_self;
    for (int p = p0; p < p1; p++) {
        int s = ei[g_eperm2[p]];
        float a = g_asrc[s * 4 + hd] + adst_n;
        a = (a > 0.f) ? a : 0.2f * a;
        amax = fmaxf(amax, a);
    }
    // pass 2: exp-weighted aggregation
    float w = expf(a_self - amax);
    float sum = w;
    float acc = w * g_xh[(size_t)n * 64 + t];
    for (int p = p0; p < p1; p++) {
        int s = ei[g_eperm2[p]];
        float a = g_asrc[s * 4 + hd] + adst_n;
        a = (a > 0.f) ? a : 0.2f * a;
        float ww = expf(a - amax);
        sum += ww;
        acc = fmaf(ww, g_xh[(size_t)s * 64 + t], acc);
    }
    g_h2[(size_t)n * 64 + t] = fmaxf(acc / (sum + 1e-16f) + gb[t], 0.f);
}

__global__ void k_pool(const int* __restrict__ batch, const float* __restrict__ n2w,
                       const float* __restrict__ n2b) {
    int i = blockIdx.x * blockDim.x + threadIdx.x;
    if (i >= NN * HH) return;
    int n = i >> 6, j = i & 63;
    float v = (g_h2[i] - g_stats[2]) * g_stats[3] * n2w[j] + n2b[j];
    int g = batch[n];
    atomicAdd(&g_pool[g * 64 + j], v);
    if (j == 0) atomicAdd(&g_gcnt[g], 1);
}

__global__ void k_head(const float* __restrict__ lw, const float* __restrict__ lb,
                       float* __restrict__ out) {
    int g = blockIdx.x, t = threadIdx.x;
    float c = fmaxf((float)g_gcnt[g], 1.f);
    float v = (g_pool[g * 64 + t] / c) * lw[t];
    __shared__ float sm[64];
    sm[t] = v;
    __syncthreads();
    for (int off = 32; off; off >>= 1) {
        if (t < off) sm[t] += sm[t + off];
        __syncthreads();
    }
    if (t == 0) out[g] = sm[0] + lb[0];
}

// ---------------- launch ----------------
extern "C" void kernel_launch(void* const* d_in, const int* in_sizes, int n_in,
                              void* d_out, int out_size) {
    const float* x    = (const float*)d_in[0];
    const int*   ei   = (const int*)d_in[1];
    const float* ea   = (const float*)d_in[2];
    const int*   batch= (const int*)d_in[3];
    const float* enw1 = (const float*)d_in[4];
    const float* enb1 = (const float*)d_in[5];
    const float* enw2 = (const float*)d_in[6];
    const float* enb2 = (const float*)d_in[7];
    const float* rootw= (const float*)d_in[8];
    const float* convb= (const float*)d_in[9];
    const float* n1w  = (const float*)d_in[10];
    const float* n1b  = (const float*)d_in[11];
    const float* gatw = (const float*)d_in[12];
    const float* attS = (const float*)d_in[13];
    const float* attD = (const float*)d_in[14];
    const float* gatb = (const float*)d_in[15];
    const float* n2w  = (const float*)d_in[16];
    const float* n2b  = (const float*)d_in[17];
    const float* linw = (const float*)d_in[18];
    const float* linb = (const float*)d_in[19];
    float* out = (float*)d_out;

    static void *p_agg = 0, *p_cnt = 0, *p_deg = 0, *p_pool = 0, *p_gcnt = 0;
    static cudaStream_t s2;
    static cudaEvent_t ev_begin, evq[NB], evm[NB];
    static int init_done = 0;
    if (!init_done) {
        cudaGetSymbolAddress(&p_agg,  g_agg);
        cudaGetSymbolAddress(&p_cnt,  g_cnt);
        cudaGetSymbolAddress(&p_deg,  g_deg);
        cudaGetSymbolAddress(&p_pool, g_pool);
        cudaGetSymbolAddress(&p_gcnt, g_gcnt);
        cudaStreamCreateWithFlags(&s2, cudaStreamNonBlocking);
        cudaEventCreateWithFlags(&ev_begin, cudaEventDisableTiming);
        for (int b = 0; b < NB; b++) {
            cudaEventCreateWithFlags(&evq[b], cudaEventDisableTiming);
            cudaEventCreateWithFlags(&evm[b], cudaEventDisableTiming);
        }
        init_done = 1;
    }

    cudaMemsetAsync(p_agg,  0, (size_t)NN * HH * 4, 0);
    cudaMemsetAsync(p_cnt,  0, (size_t)NN * 4, 0);
    cudaMemsetAsync(p_deg,  0, (size_t)NN * 4, 0);
    cudaMemsetAsync(p_pool, 0, (size_t)NGRP * HH * 4, 0);
    cudaMemsetAsync(p_gcnt, 0, (size_t)NGRP * 4, 0);

    k_hist<<<(EE + 255) / 256, 256>>>(ei);
    k_scan<<<1, 1024>>>();
    k_scatter<<<(EE + 255) / 256, 256>>>(ei);

    // fork producer stream after CSR build
    cudaEventRecord(ev_begin, 0);
    cudaStreamWaitEvent(s2, ev_begin, 0);

    dim3 qg((NPB + 31) / 32, 64);
    for (int b = 0; b < NB; b++) {
        int n0 = b * NPB;
        int which = b & 1;
        if (b >= 2) cudaStreamWaitEvent(s2, evm[b - 2], 0);  // buffer free?
        k_Q<<<qg, 256, 0, s2>>>(x, enw2, n0, which);
        cudaEventRecord(evq[b], s2);
        cudaStreamWaitEvent(0, evq[b], 0);                   // Q ready?
        k_msg<<<NPB, 256>>>(x, ea, ei, enw1, enb1, enb2, n0, which);
        cudaEventRecord(evm[b], 0);
    }

    k_conv<<<(NN * HH + 255) / 256, 256>>>(x, rootw, convb);

    k_redpart<<<NPART, 256>>>(0);
    k_redfin<<<1, NPART>>>(0);

    k_gatprep<<<NN, 64>>>(gatw, attS, attD, n1w, n1b);
    k_gatfused<<<NN, 64>>>(ei, gatb);

    k_redpart<<<NPART, 256>>>(1);
    k_redfin<<<1, NPART>>>(1);

    k_pool<<<(NN * HH + 255) / 256, 256>>>(batch, n2w, n2b);
    k_head<<<NGRP, 64>>>(linw, linb, out);
}